// round 14
// baseline (speedup 1.0000x reference)
#include <cuda_runtime.h>
#include <cuda_fp16.h>
#include <stdint.h>
#include <math.h>

#define N      8192
#define FIN    256
#define FOUT   128
#define MT     64
#define KC     64
#define KSLICE 4096
#define NC     64

// smem layout (bytes)
#define OFF_EPEN 0               // 4096 x uint32 (half2{ep,en}) = 16384
#define B_STG    16384           // 128 x 128 (swizzled)
#define OFF_B    16384           // 3 stages -> 65536
#define OFF_A    65536           // 64 x 128 (swizzled) = 8192
#define SMEM_TOTAL 73728

__device__ float g_Wh[(size_t)N * FOUT];
__device__ __half g_WhT[(size_t)FOUT * N];
__device__ float g_s1[N], g_s2[N];
__device__ uint32_t g_EPEN[N];       // half2 {exp(s2-s2max), exp(0.2(s2-s2max))}
__device__ float4 g_rc4[N];          // {eth, r1p, r1n, 0}
__device__ float g_s2max;
__device__ float g_part[2][(size_t)N * FOUT];
__device__ float g_Zpart[2][N];

__device__ __forceinline__ uint32_t smem_u32(const void* p) {
    uint32_t a;
    asm("{ .reg .u64 t; cvta.to.shared.u64 t, %1; cvt.u32.u64 %0, t; }" : "=r"(a) : "l"(p));
    return a;
}
__device__ __forceinline__ void cpa16(uint32_t s, const void* g) {
    asm volatile("cp.async.cg.shared.global [%0], [%1], 16;" :: "r"(s), "l"(g));
}
#define CP_COMMIT() asm volatile("cp.async.commit_group;" ::: "memory")
#define CP_WAIT1()  asm volatile("cp.async.wait_group 1;" ::: "memory")

__device__ __forceinline__ void ldsm4(uint32_t* r, uint32_t addr) {
    asm volatile("ldmatrix.sync.aligned.m8n8.x4.shared.b16 {%0,%1,%2,%3}, [%4];"
        : "=r"(r[0]), "=r"(r[1]), "=r"(r[2]), "=r"(r[3]) : "r"(addr));
}
__device__ __forceinline__ void mma16816(float* d, const uint32_t* a, const uint32_t* b) {
    asm volatile("mma.sync.aligned.m16n8k16.row.col.f32.f16.f16.f32 "
        "{%0,%1,%2,%3}, {%4,%5,%6,%7}, {%8,%9}, {%0,%1,%2,%3};"
        : "+f"(d[0]), "+f"(d[1]), "+f"(d[2]), "+f"(d[3])
        : "r"(a[0]), "r"(a[1]), "r"(a[2]), "r"(a[3]), "r"(b[0]), "r"(b[1]));
}

// ---- Wh = h @ W^T (fp32) + fp16 transpose + fused s1/s2 ----
__global__ void __launch_bounds__(128) k_wh(const float* __restrict__ h,
                                            const float* __restrict__ W,
                                            const float* __restrict__ a1,
                                            const float* __restrict__ a2) {
    __shared__ float hs[32][FIN];
    __shared__ float red[4][32][2];
    const int row0 = blockIdx.x * 32, t = threadIdx.x;
    const int wid = t >> 5, lane = t & 31;
    const float4* h4 = (const float4*)(h + (size_t)row0 * FIN);
    float4* hs4 = (float4*)&hs[0][0];
    #pragma unroll
    for (int u = 0; u < 16; u++) hs4[t + u * 128] = h4[t + u * 128];
    __syncthreads();
    const float4* W4 = (const float4*)(W + (size_t)t * FIN);
    float acc[32];
    #pragma unroll
    for (int r = 0; r < 32; r++) acc[r] = 0.f;
    for (int k0 = 0; k0 < FIN; k0 += 32) {
        float4 wv[8];
        #pragma unroll
        for (int c = 0; c < 8; c++) wv[c] = W4[k0 / 4 + c];
        #pragma unroll
        for (int r = 0; r < 32; r++) {
            const float4* hv4 = (const float4*)&hs[r][k0];
            #pragma unroll
            for (int c = 0; c < 8; c++) {
                float4 hv = hv4[c];
                acc[r] += hv.x * wv[c].x; acc[r] += hv.y * wv[c].y;
                acc[r] += hv.z * wv[c].z; acc[r] += hv.w * wv[c].w;
            }
        }
    }
    const float a1v = __ldg(&a1[t]), a2v = __ldg(&a2[t]);
    #pragma unroll
    for (int r = 0; r < 32; r++) {
        g_Wh[(size_t)(row0 + r) * FOUT + t] = acc[r];
        g_WhT[(size_t)t * N + row0 + r] = __float2half_rn(acc[r]);
        float p1 = acc[r] * a1v, p2 = acc[r] * a2v;
        #pragma unroll
        for (int o = 16; o > 0; o >>= 1) {
            p1 += __shfl_xor_sync(~0u, p1, o);
            p2 += __shfl_xor_sync(~0u, p2, o);
        }
        if (lane == 0) { red[wid][r][0] = p1; red[wid][r][1] = p2; }
    }
    __syncthreads();
    if (t < 32) {
        g_s1[row0 + t] = red[0][t][0] + red[1][t][0] + red[2][t][0] + red[3][t][0];
        g_s2[row0 + t] = red[0][t][1] + red[1][t][1] + red[2][t][1] + red[3][t][1];
    }
}

// s2max reduce (single block)
__global__ void __launch_bounds__(1024) k_max() {
    __shared__ float red[1024];
    const int t = threadIdx.x;
    float m = -1e30f;
    #pragma unroll
    for (int u = 0; u < 8; u++) m = fmaxf(m, g_s2[t + u * 1024]);
    red[t] = m; __syncthreads();
    for (int s = 512; s > 0; s >>= 1) {
        if (t < s) red[t] = fmaxf(red[t], red[t + s]);
        __syncthreads();
    }
    if (t == 0) g_s2max = red[0];
}

// shifted factors: w_ij = adj ? (ep_j >= eth_i ? r1p_i*ep_j : r1n_i*en_j) : 0
__global__ void __launch_bounds__(256) k_fact() {
    const int i = blockIdx.x * 256 + threadIdx.x;
    const float s2max = g_s2max;
    const float s1 = g_s1[i], s2 = g_s2[i];
    const float tt = s1 + s2max;
    const float lr = (tt > 0.f ? tt : 0.2f * tt);
    const float L = 6.9314718f;           // ln 1024
    g_rc4[i] = make_float4(expf(-s1 - s2max),
                           expf(tt - lr + L),
                           expf(0.2f * tt - lr + L), 0.f);
    __half2 p = __floats2half2_rn(expf(s2 - s2max), expf(0.2f * (s2 - s2max)));
    g_EPEN[i] = *(uint32_t*)&p;
}

// ---- fused masked-softmax attention GEMM: 256 thr, MT=64, 2 CTA/SM, adj LDG ----
__global__ void __launch_bounds__(256, 2) k_attn(const int* __restrict__ adj) {
    extern __shared__ char smem[];
    const uint32_t sb = smem_u32(smem);
    const int t = threadIdx.x, wid = t >> 5, lane = t & 31;
    const int mt_ = blockIdx.x >> 1, slice = blockIdx.x & 1;
    const int row0 = mt_ * MT, jbase = slice * KSLICE;

    auto fill_B = [&](int c, int s) {
        const size_t gcol = (size_t)jbase + (size_t)c * KC;
        #pragma unroll
        for (int k = 0; k < 4; k++) {
            const int id = t + k * 256;
            const int f = id >> 3, cc = id & 7;
            cpa16(sb + OFF_B + s * B_STG + f * 128 + ((cc ^ (f & 7)) << 4),
                  g_WhT + (size_t)f * N + gcol + cc * 8);
        }
    };

    // gen mapping: 4 threads per row, 16 j's each
    const int m = t >> 2, jq = (t & 3) * 16;
    const float4 rc = __ldg(&g_rc4[row0 + m]);     // {eth, r1p, r1n}
    float zacc = 0.f;
    const int4* const aptr = (const int4*)(adj + (size_t)(row0 + m) * N + jbase + jq);

    // prologue: EPEN + B stages 0,1; adj chunk 0 into regs
    {
        #pragma unroll
        for (int k = 0; k < 4; k++) {
            const int ch = t + k * 256;
            cpa16(sb + OFF_EPEN + ch * 16, g_EPEN + jbase + ch * 4);
        }
        fill_B(0, 0); CP_COMMIT();
        fill_B(1, 1); CP_COMMIT();
    }
    int4 abuf[4];
    #pragma unroll
    for (int u = 0; u < 4; u++) abuf[u] = __ldg(aptr + u);

    // mma mapping: 8 warps = 2x4, warp tile 32 x 32
    const int r0 = (wid >> 2) * 32, c0 = (wid & 3) * 32;
    const int rowA = r0 + (lane & 15);
    const int rowB0 = c0 + (lane & 7) + ((lane >> 4) & 1) * 8;
    const int uA = lane >> 4, uB = (lane >> 3) & 1;
    float acc[2][4][4];
    #pragma unroll
    for (int i = 0; i < 2; i++)
        #pragma unroll
        for (int j = 0; j < 4; j++)
            #pragma unroll
            for (int q = 0; q < 4; q++) acc[i][j][q] = 0.f;

    #pragma unroll 1
    for (int c = 0; c < NC; c++) {
        CP_WAIT1();          // B(c) (+EPEN at c=0) resident
        __syncthreads();     // all warps done with mma(c-1) before A overwrite

        // ---- gen chunk c: 16 w's per thread into swizzled A ----
        {
            const uint4* ee = (const uint4*)(smem + OFF_EPEN + (c * KC + jq) * 4);
            uint32_t v[8];
            #pragma unroll
            for (int u = 0; u < 4; u++) {
                const int4 a4 = abuf[u];
                const uint4 e4 = ee[u];
                float2 f0 = __half22float2(*(const __half2*)&e4.x);
                float2 f1 = __half22float2(*(const __half2*)&e4.y);
                float2 f2 = __half22float2(*(const __half2*)&e4.z);
                float2 f3 = __half22float2(*(const __half2*)&e4.w);
                float w0 = (f0.x >= rc.x) ? rc.y * f0.x : rc.z * f0.y; if (a4.x == 0) w0 = 0.f;
                float w1 = (f1.x >= rc.x) ? rc.y * f1.x : rc.z * f1.y; if (a4.y == 0) w1 = 0.f;
                float w2 = (f2.x >= rc.x) ? rc.y * f2.x : rc.z * f2.y; if (a4.z == 0) w2 = 0.f;
                float w3 = (f3.x >= rc.x) ? rc.y * f3.x : rc.z * f3.y; if (a4.w == 0) w3 = 0.f;
                zacc += (w0 + w1) + (w2 + w3);
                __half2 p0 = __floats2half2_rn(w0, w1), p1 = __floats2half2_rn(w2, w3);
                v[2 * u] = *(uint32_t*)&p0; v[2 * u + 1] = *(uint32_t*)&p1;
            }
            const int u0 = (t & 3) * 2;
            char* const arow = smem + OFF_A + m * 128;
            *(uint4*)(arow + (((u0)     ^ (m & 7)) << 4)) = make_uint4(v[0], v[1], v[2], v[3]);
            *(uint4*)(arow + (((u0 + 1) ^ (m & 7)) << 4)) = make_uint4(v[4], v[5], v[6], v[7]);
        }
        // prefetch adj chunk c+1 (latency hidden under sync + fill + mma)
        if (c + 1 < NC) {
            const int4* p = aptr + (size_t)(c + 1) * 16;
            #pragma unroll
            for (int u = 0; u < 4; u++) abuf[u] = __ldg(p + u);
        }
        __syncthreads();     // A published

        if (c + 2 < NC) fill_B(c + 2, (c + 2) % 3);
        CP_COMMIT();

        // ---- mma chunk c ----
        const uint32_t bB = sb + OFF_B + (c % 3) * B_STG;
        #pragma unroll
        for (int kk = 0; kk < 4; kk++) {
            uint32_t a[2][4], b[2][4];
            #pragma unroll
            for (int mi = 0; mi < 2; mi++) {
                const int rA = rowA + mi * 16;
                ldsm4(a[mi], sb + OFF_A + rA * 128 + (((kk * 2 + uA) ^ (rA & 7)) << 4));
            }
            #pragma unroll
            for (int ng = 0; ng < 2; ng++) {
                const int rB = rowB0 + ng * 16;
                ldsm4(b[ng], bB + rB * 128 + (((kk * 2 + uB) ^ (rB & 7)) << 4));
            }
            #pragma unroll
            for (int mi = 0; mi < 2; mi++)
                #pragma unroll
                for (int ng = 0; ng < 2; ng++) {
                    mma16816(acc[mi][2 * ng], a[mi], b[ng]);
                    mma16816(acc[mi][2 * ng + 1], a[mi], b[ng] + 2);
                }
        }
    }

    // Z reduce across 4 threads sharing a row
    zacc += __shfl_xor_sync(~0u, zacc, 1);
    zacc += __shfl_xor_sync(~0u, zacc, 2);
    if ((t & 3) == 0) g_Zpart[slice][row0 + m] = zacc;

    // epilogue
    const int quad = lane >> 2, qc = (lane & 3) * 2;
    #pragma unroll
    for (int mi = 0; mi < 2; mi++) {
        const int rg = row0 + r0 + mi * 16 + quad;
        #pragma unroll
        for (int nt = 0; nt < 4; nt++) {
            const int col = c0 + nt * 8 + qc;
            float* p = g_part[slice] + (size_t)rg * FOUT + col;
            *(float2*)p = make_float2(acc[mi][nt][0], acc[mi][nt][1]);
            *(float2*)(p + 8 * FOUT) = make_float2(acc[mi][nt][2], acc[mi][nt][3]);
        }
    }
}

// combine K-slices: out = elu((p0+p1)/(z0+z1))
__global__ void __launch_bounds__(256) k_final(float* __restrict__ out) {
    const int idx = blockIdx.x * 256 + threadIdx.x;
    const int row = idx >> 5, c4 = (idx & 31) * 4;
    const size_t off = (size_t)row * FOUT + c4;
    const float4 p0 = *(const float4*)(g_part[0] + off);
    const float4 p1 = *(const float4*)(g_part[1] + off);
    const float inv = 1.0f / (g_Zpart[0][row] + g_Zpart[1][row]);
    float4 o; float v;
    v = (p0.x + p1.x) * inv; o.x = v > 0.f ? v : expm1f(v);
    v = (p0.y + p1.y) * inv; o.y = v > 0.f ? v : expm1f(v);
    v = (p0.z + p1.z) * inv; o.z = v > 0.f ? v : expm1f(v);
    v = (p0.w + p1.w) * inv; o.w = v > 0.f ? v : expm1f(v);
    *(float4*)(out + off) = o;
}

extern "C" void kernel_launch(void* const* d_in, const int* in_sizes, int n_in,
                              void* d_out, int out_size) {
    const float* h   = (const float*)d_in[0];
    const int*   adj = (const int*)d_in[1];
    const float* W   = (const float*)d_in[2];
    const float* a1  = (const float*)d_in[3];
    const float* a2  = (const float*)d_in[4];
    float* out = (float*)d_out;

    cudaFuncSetAttribute(k_attn, cudaFuncAttributeMaxDynamicSharedMemorySize, SMEM_TOTAL);

    k_wh   <<<N / 32, 128>>>(h, W, a1, a2);
    k_max  <<<1, 1024>>>();
    k_fact <<<N / 256, 256>>>();
    k_attn <<<256, 256, SMEM_TOTAL>>>(adj);   // position 3 -> ncu captures this
    k_final<<<N * FOUT / 1024, 256>>>(out);
}

// round 15
// speedup vs baseline: 1.2279x; 1.2279x over previous
#include <cuda_runtime.h>
#include <cuda_fp16.h>
#include <stdint.h>
#include <math.h>

#define N      8192
#define FIN    256
#define FOUT   128
#define MT     64
#define KC     64
#define KSLICE 4096
#define NC     64

// smem layout (bytes) for k_attn
#define ADJ_STG 17408            // 64 x 272
#define OFF_ADJ 0                // 2 stages -> 34816
#define B_STG   16384            // 128 x 128 (swizzled)
#define OFF_B   34816            // 3 stages -> 83968
#define A_STG   8192             // 64 x 128 (swizzled)
#define OFF_A   83968            // 2 stages -> 100352
#define SMEM_TOTAL 100352

__device__ float g_Wh[(size_t)N * FOUT];
__device__ __half g_WhT[(size_t)FOUT * N];
__device__ float g_s1[N], g_s2[N];
__device__ uint32_t g_EPEN[N];       // half2 {exp(s2-s2max), exp(0.2(s2-s2max))}
__device__ float4 g_rc4[N];          // {eth, r1p, r1n, 0}
__device__ float g_s2max;
__device__ float g_part[2][(size_t)N * FOUT];
__device__ float g_Zpart[2][N];

__device__ __forceinline__ uint32_t smem_u32(const void* p) {
    uint32_t a;
    asm("{ .reg .u64 t; cvta.to.shared.u64 t, %1; cvt.u32.u64 %0, t; }" : "=r"(a) : "l"(p));
    return a;
}
__device__ __forceinline__ void cpa16(uint32_t s, const void* g) {
    asm volatile("cp.async.cg.shared.global [%0], [%1], 16;" :: "r"(s), "l"(g));
}
#define CP_COMMIT() asm volatile("cp.async.commit_group;" ::: "memory")
#define CP_WAIT0()  asm volatile("cp.async.wait_group 0;" ::: "memory")

__device__ __forceinline__ void ldsm4(uint32_t* r, uint32_t addr) {
    asm volatile("ldmatrix.sync.aligned.m8n8.x4.shared.b16 {%0,%1,%2,%3}, [%4];"
        : "=r"(r[0]), "=r"(r[1]), "=r"(r[2]), "=r"(r[3]) : "r"(addr));
}
__device__ __forceinline__ void mma16816(float* d, const uint32_t* a, const uint32_t* b) {
    asm volatile("mma.sync.aligned.m16n8k16.row.col.f32.f16.f16.f32 "
        "{%0,%1,%2,%3}, {%4,%5,%6,%7}, {%8,%9}, {%0,%1,%2,%3};"
        : "+f"(d[0]), "+f"(d[1]), "+f"(d[2]), "+f"(d[3])
        : "r"(a[0]), "r"(a[1]), "r"(a[2]), "r"(a[3]), "r"(b[0]), "r"(b[1]));
}

// ---- Wh = h @ W^T: 256 thr k-split, smem-transposed WhT write, fused s1/s2 ----
__global__ void __launch_bounds__(256) k_wh(const float* __restrict__ h,
                                            const float* __restrict__ W,
                                            const float* __restrict__ a1,
                                            const float* __restrict__ a2) {
    __shared__ float hs[32][FIN];                 // 32 KB
    __shared__ float part[32][128];               // 16 KB (kh=1 partials)
    __shared__ __align__(16) __half hT[128 * 40]; // 10 KB transpose buffer
    __shared__ float red[4][32][2];
    const int row0 = blockIdx.x * 32, t = threadIdx.x;
    const int f = t & 127, kh = t >> 7;

    const float4* h4 = (const float4*)(h + (size_t)row0 * FIN);
    float4* hs4 = (float4*)&hs[0][0];
    #pragma unroll
    for (int u = 0; u < 8; u++) hs4[t + u * 256] = h4[t + u * 256];
    __syncthreads();

    const float4* W4 = (const float4*)(W + (size_t)f * FIN) + kh * 32;
    float acc[32];
    #pragma unroll
    for (int r = 0; r < 32; r++) acc[r] = 0.f;
    #pragma unroll
    for (int k0 = 0; k0 < 128; k0 += 32) {
        float4 wv[8];
        #pragma unroll
        for (int c = 0; c < 8; c++) wv[c] = W4[k0 / 4 + c];
        #pragma unroll
        for (int r = 0; r < 32; r++) {
            const float4* hv4 = (const float4*)&hs[r][kh * 128 + k0];
            #pragma unroll
            for (int c = 0; c < 8; c++) {
                float4 hv = hv4[c];
                acc[r] += hv.x * wv[c].x; acc[r] += hv.y * wv[c].y;
                acc[r] += hv.z * wv[c].z; acc[r] += hv.w * wv[c].w;
            }
        }
    }
    if (kh == 1) {
        #pragma unroll
        for (int r = 0; r < 32; r++) part[r][f] = acc[r];
    }
    __syncthreads();
    if (kh == 0) {
        const int wid = t >> 5, lane = t & 31;
        const float a1v = __ldg(&a1[f]), a2v = __ldg(&a2[f]);
        #pragma unroll
        for (int r = 0; r < 32; r++) {
            acc[r] += part[r][f];
            g_Wh[(size_t)(row0 + r) * FOUT + f] = acc[r];
            hT[f * 40 + r] = __float2half_rn(acc[r]);
            float p1 = acc[r] * a1v, p2 = acc[r] * a2v;
            #pragma unroll
            for (int o = 16; o > 0; o >>= 1) {
                p1 += __shfl_xor_sync(~0u, p1, o);
                p2 += __shfl_xor_sync(~0u, p2, o);
            }
            if (lane == 0) { red[wid][r][0] = p1; red[wid][r][1] = p2; }
        }
    }
    __syncthreads();
    // coalesced WhT write: 32B per thread
    {
        const int f2 = t >> 1, seg = t & 1;
        const uint4* s = (const uint4*)(hT + f2 * 40 + seg * 16);
        uint4* d = (uint4*)(g_WhT + (size_t)f2 * N + row0 + seg * 16);
        d[0] = s[0]; d[1] = s[1];
    }
    if (t < 32) {
        g_s1[row0 + t] = red[0][t][0] + red[1][t][0] + red[2][t][0] + red[3][t][0];
        g_s2[row0 + t] = red[0][t][1] + red[1][t][1] + red[2][t][1] + red[3][t][1];
    }
}

// s2max reduce (single block)
__global__ void __launch_bounds__(1024) k_max() {
    __shared__ float red[1024];
    const int t = threadIdx.x;
    float m = -1e30f;
    #pragma unroll
    for (int u = 0; u < 8; u++) m = fmaxf(m, g_s2[t + u * 1024]);
    red[t] = m; __syncthreads();
    for (int s = 512; s > 0; s >>= 1) {
        if (t < s) red[t] = fmaxf(red[t], red[t + s]);
        __syncthreads();
    }
    if (t == 0) g_s2max = red[0];
}

// shifted factors: w_ij = adj ? (ep_j >= eth_i ? r1p_i*ep_j : r1n_i*en_j) : 0
__global__ void __launch_bounds__(256) k_fact() {
    const int i = blockIdx.x * 256 + threadIdx.x;
    const float s2max = g_s2max;
    const float s1 = g_s1[i], s2 = g_s2[i];
    const float tt = s1 + s2max;
    const float lr = (tt > 0.f ? tt : 0.2f * tt);
    const float L = 6.9314718f;           // ln 1024
    g_rc4[i] = make_float4(expf(-s1 - s2max),
                           expf(tt - lr + L),
                           expf(0.2f * tt - lr + L), 0.f);
    __half2 p = __floats2half2_rn(expf(s2 - s2max), expf(0.2f * (s2 - s2max)));
    g_EPEN[i] = *(uint32_t*)&p;
}

// ---- fused masked-softmax attention GEMM: single-sync pipelined, A double-buffer ----
__global__ void __launch_bounds__(256, 2) k_attn(const int* __restrict__ adj) {
    extern __shared__ char smem[];
    const uint32_t sb = smem_u32(smem);
    const int t = threadIdx.x, wid = t >> 5, lane = t & 31;
    const int mt_ = blockIdx.x >> 1, slice = blockIdx.x & 1;
    const int row0 = mt_ * MT, jbase = slice * KSLICE;

    auto fill_adj = [&](int c, int s) {
        const size_t gcol = (size_t)jbase + (size_t)c * KC;
        #pragma unroll
        for (int k = 0; k < 4; k++) {
            const int id = t + k * 256;
            const int r = id >> 4, cc = id & 15;
            cpa16(sb + OFF_ADJ + s * ADJ_STG + r * 272 + cc * 16,
                  adj + (size_t)(row0 + r) * N + gcol + cc * 4);
        }
    };
    auto fill_B = [&](int c, int s) {
        const size_t gcol = (size_t)jbase + (size_t)c * KC;
        #pragma unroll
        for (int k = 0; k < 4; k++) {
            const int id = t + k * 256;
            const int f = id >> 3, cc = id & 7;
            cpa16(sb + OFF_B + s * B_STG + f * 128 + ((cc ^ (f & 7)) << 4),
                  g_WhT + (size_t)f * N + gcol + cc * 8);
        }
    };

    // gen mapping: 4 threads per row, 16 j's each
    const int m = t >> 2, jq = (t & 3) * 16;
    const float4 rc = __ldg(&g_rc4[row0 + m]);     // {eth, r1p, r1n}
    float zacc = 0.f;

    auto gen = [&](int c) {
        const int sA = c & 1;
        const int4* ar = (const int4*)(smem + OFF_ADJ + sA * ADJ_STG + m * 272 + jq * 4);
        const uint4* eg = (const uint4*)(g_EPEN + jbase + c * KC + jq);
        uint32_t v[8];
        #pragma unroll
        for (int u = 0; u < 4; u++) {
            const int4 a4 = ar[u];
            const uint4 e4 = __ldg(eg + u);
            float2 f0 = __half22float2(*(const __half2*)&e4.x);
            float2 f1 = __half22float2(*(const __half2*)&e4.y);
            float2 f2 = __half22float2(*(const __half2*)&e4.z);
            float2 f3 = __half22float2(*(const __half2*)&e4.w);
            float w0 = (f0.x >= rc.x) ? rc.y * f0.x : rc.z * f0.y; if (a4.x == 0) w0 = 0.f;
            float w1 = (f1.x >= rc.x) ? rc.y * f1.x : rc.z * f1.y; if (a4.y == 0) w1 = 0.f;
            float w2 = (f2.x >= rc.x) ? rc.y * f2.x : rc.z * f2.y; if (a4.z == 0) w2 = 0.f;
            float w3 = (f3.x >= rc.x) ? rc.y * f3.x : rc.z * f3.y; if (a4.w == 0) w3 = 0.f;
            zacc += (w0 + w1) + (w2 + w3);
            __half2 p0 = __floats2half2_rn(w0, w1), p1 = __floats2half2_rn(w2, w3);
            v[2 * u] = *(uint32_t*)&p0; v[2 * u + 1] = *(uint32_t*)&p1;
        }
        const int u0 = (t & 3) * 2;
        char* const arow = smem + OFF_A + sA * A_STG + m * 128;
        *(uint4*)(arow + (((u0)     ^ (m & 7)) << 4)) = make_uint4(v[0], v[1], v[2], v[3]);
        *(uint4*)(arow + (((u0 + 1) ^ (m & 7)) << 4)) = make_uint4(v[4], v[5], v[6], v[7]);
    };

    // prologue: adj/B stages 0,1; gen(0)
    fill_adj(0, 0); fill_adj(1, 1); fill_B(0, 0); fill_B(1, 1); CP_COMMIT();
    CP_WAIT0();
    __syncthreads();
    gen(0);

    // mma mapping: 8 warps = 2x4, warp tile 32 x 32
    const int r0 = (wid >> 2) * 32, c0 = (wid & 3) * 32;
    const int rowA = r0 + (lane & 15);
    const int rowB0 = c0 + (lane & 7) + ((lane >> 4) & 1) * 8;
    const int uA = lane >> 4, uB = (lane >> 3) & 1;
    float acc[2][4][4];
    #pragma unroll
    for (int i = 0; i < 2; i++)
        #pragma unroll
        for (int j = 0; j < 4; j++)
            #pragma unroll
            for (int q = 0; q < 4; q++) acc[i][j][q] = 0.f;

    #pragma unroll 1
    for (int c = 0; c < NC; c++) {
        CP_WAIT0();          // adj(c+1), B(c+1) (and older) resident
        __syncthreads();     // publish A[c&1]; all mma(c-1) readers done
        if (c + 2 < NC) { fill_adj(c + 2, c & 1); fill_B(c + 2, (c + 2) % 3); }
        CP_COMMIT();

        // ---- mma chunk c (warps slip: gen below overlaps other warps' mma) ----
        const uint32_t aOff = sb + OFF_A + (c & 1) * A_STG;
        const uint32_t bB = sb + OFF_B + (c % 3) * B_STG;
        #pragma unroll
        for (int kk = 0; kk < 4; kk++) {
            uint32_t a[2][4], b[2][4];
            #pragma unroll
            for (int mi = 0; mi < 2; mi++) {
                const int rA = rowA + mi * 16;
                ldsm4(a[mi], aOff + rA * 128 + (((kk * 2 + uA) ^ (rA & 7)) << 4));
            }
            #pragma unroll
            for (int ng = 0; ng < 2; ng++) {
                const int rB = rowB0 + ng * 16;
                ldsm4(b[ng], bB + rB * 128 + (((kk * 2 + uB) ^ (rB & 7)) << 4));
            }
            #pragma unroll
            for (int mi = 0; mi < 2; mi++)
                #pragma unroll
                for (int ng = 0; ng < 2; ng++) {
                    mma16816(acc[mi][2 * ng], a[mi], b[ng]);
                    mma16816(acc[mi][2 * ng + 1], a[mi], b[ng] + 2);
                }
        }

        if (c + 1 < NC) gen(c + 1);    // writes A[(c+1)&1] (mma(c-1) on it finished pre-sync)
    }

    // Z reduce across 4 threads sharing a row
    zacc += __shfl_xor_sync(~0u, zacc, 1);
    zacc += __shfl_xor_sync(~0u, zacc, 2);
    if ((t & 3) == 0) g_Zpart[slice][row0 + m] = zacc;

    // epilogue
    const int quad = lane >> 2, qc = (lane & 3) * 2;
    #pragma unroll
    for (int mi = 0; mi < 2; mi++) {
        const int rg = row0 + r0 + mi * 16 + quad;
        #pragma unroll
        for (int nt = 0; nt < 4; nt++) {
            const int col = c0 + nt * 8 + qc;
            float* p = g_part[slice] + (size_t)rg * FOUT + col;
            *(float2*)p = make_float2(acc[mi][nt][0], acc[mi][nt][1]);
            *(float2*)(p + 8 * FOUT) = make_float2(acc[mi][nt][2], acc[mi][nt][3]);
        }
    }
}

// combine K-slices: out = elu((p0+p1)/(z0+z1))
__global__ void __launch_bounds__(256) k_final(float* __restrict__ out) {
    const int idx = blockIdx.x * 256 + threadIdx.x;
    const int row = idx >> 5, c4 = (idx & 31) * 4;
    const size_t off = (size_t)row * FOUT + c4;
    const float4 p0 = *(const float4*)(g_part[0] + off);
    const float4 p1 = *(const float4*)(g_part[1] + off);
    const float inv = 1.0f / (g_Zpart[0][row] + g_Zpart[1][row]);
    float4 o; float v;
    v = (p0.x + p1.x) * inv; o.x = v > 0.f ? v : expm1f(v);
    v = (p0.y + p1.y) * inv; o.y = v > 0.f ? v : expm1f(v);
    v = (p0.z + p1.z) * inv; o.z = v > 0.f ? v : expm1f(v);
    v = (p0.w + p1.w) * inv; o.w = v > 0.f ? v : expm1f(v);
    *(float4*)(out + off) = o;
}

extern "C" void kernel_launch(void* const* d_in, const int* in_sizes, int n_in,
                              void* d_out, int out_size) {
    const float* h   = (const float*)d_in[0];
    const int*   adj = (const int*)d_in[1];
    const float* W   = (const float*)d_in[2];
    const float* a1  = (const float*)d_in[3];
    const float* a2  = (const float*)d_in[4];
    float* out = (float*)d_out;

    cudaFuncSetAttribute(k_attn, cudaFuncAttributeMaxDynamicSharedMemorySize, SMEM_TOTAL);

    k_wh   <<<N / 32, 256>>>(h, W, a1, a2);
    k_max  <<<1, 1024>>>();
    k_fact <<<N / 256, 256>>>();
    k_attn <<<256, 256, SMEM_TOTAL>>>(adj);   // position 3 -> ncu captures this
    k_final<<<N * FOUT / 1024, 256>>>(out);
}